// round 4
// baseline (speedup 1.0000x reference)
#include <cuda_runtime.h>
#include <cuda_bf16.h>
#include <stdint.h>

// Problem constants
#define BSZ 2
#define TT  1024
#define DD  768
#define KK  24
#define SS  128
#define KX  5
#define NCH (BSZ*DD)   // 1536 channels

// Static device scratch
__device__ float g_u[NCH * TT];        // u[(b*768+d)*1024 + t]
__device__ float g_wt[DD * SS];        // folded readout weight w~[d][s]
__device__ float g_gd[DD * KX];        // folded direct taps gdir[d][j]
__device__ float g_A[SS];              // resolved decay A
__device__ float g_Bm[SS];             // resolved input map Bm

// ---------------------------------------------------------------------------
// Kernel 0: resolve which 128-vector is A (uniform(0,1): all >= 0) and which
// is Bm (normal/128: has negatives). No-op if binding already correct.
// ---------------------------------------------------------------------------
__global__ void resolve_kernel(const float* __restrict__ p0,
                               const float* __restrict__ p1)
{
    __shared__ int neg0;
    if (threadIdx.x == 0) neg0 = 0;
    __syncthreads();
    if (p0[threadIdx.x] < 0.f) atomicAdd(&neg0, 1);
    __syncthreads();
    const float* Ap = (neg0 > 0) ? p1 : p0;
    const float* Bp = (neg0 > 0) ? p0 : p1;
    g_A[threadIdx.x]  = Ap[threadIdx.x];
    g_Bm[threadIdx.x] = Bp[threadIdx.x];
}

// ---------------------------------------------------------------------------
// Kernel 1: fold weights.
//   wt[d][s] = Bm[s] * sum_k Mf[k][d] * (C[k][s] + C[K+k][s])
//   gd[d][j] = sum_k Mf[k][d] * (Mdir[k][j] + Mdir[K+k][j])
// ---------------------------------------------------------------------------
__global__ void prep_kernel(const float* __restrict__ Mf,    // (24,768)
                            const float* __restrict__ C,     // (48,128)
                            const float* __restrict__ Mdir)  // (48,5)
{
    int d = blockIdx.x;
    int s = threadIdx.x;          // 128 threads
    float acc = 0.f;
#pragma unroll
    for (int k = 0; k < KK; ++k) {
        float mf = Mf[k * DD + d];
        acc += mf * (C[k * SS + s] + C[(KK + k) * SS + s]);
    }
    g_wt[d * SS + s] = acc * g_Bm[s];
    if (s < KX) {
        float a = 0.f;
#pragma unroll
        for (int k = 0; k < KK; ++k) {
            float mf = Mf[k * DD + d];
            a += mf * (Mdir[k * KX + s] + Mdir[(KK + k) * KX + s]);
        }
        g_gd[d * KX + s] = a;
    }
}

// ---------------------------------------------------------------------------
// Kernel 2: u[(b,d),t] = sum_c x[b,t,c] * M[c,d]   (transposed-output GEMM)
// 64(t) x 64(d) tile, BK=32, 256 threads, 4x4 microtile.
// ---------------------------------------------------------------------------
__global__ __launch_bounds__(256) void gemm_kernel(const float* __restrict__ x,  // (2,1024,768)
                                                   const float* __restrict__ M)  // (768,768)
{
    __shared__ float Xs[64][33];   // [t][c]  padded
    __shared__ float Ms[32][64];   // [c][d]

    int b  = blockIdx.z;
    int t0 = blockIdx.y * 64;
    int d0 = blockIdx.x * 64;
    int tid = threadIdx.x;
    int tx = tid & 15;           // d group (4 d each)
    int ty = tid >> 4;           // t group (4 t each)

    int lc = tid & 31;           // X-load: c index
    int lt = tid >> 5;           // X-load: t row group (8 rows each)
    int ldm = tid & 63;          // M-load: d index
    int lcm = tid >> 6;          // M-load: c row group (8 rows each)

    float acc[4][4] = {};

    const float* xb = x + (size_t)(b * TT + t0) * DD;

    for (int c0 = 0; c0 < DD; c0 += 32) {
#pragma unroll
        for (int i = 0; i < 8; ++i)
            Xs[lt * 8 + i][lc] = xb[(size_t)(lt * 8 + i) * DD + c0 + lc];
#pragma unroll
        for (int i = 0; i < 8; ++i)
            Ms[lcm * 8 + i][ldm] = M[(size_t)(c0 + lcm * 8 + i) * DD + d0 + ldm];
        __syncthreads();

#pragma unroll
        for (int kk = 0; kk < 32; ++kk) {
            float4 m4 = *(const float4*)&Ms[kk][tx * 4];
            float x0 = Xs[ty * 4 + 0][kk];
            float x1 = Xs[ty * 4 + 1][kk];
            float x2 = Xs[ty * 4 + 2][kk];
            float x3 = Xs[ty * 4 + 3][kk];
            acc[0][0] = fmaf(x0, m4.x, acc[0][0]);
            acc[0][1] = fmaf(x0, m4.y, acc[0][1]);
            acc[0][2] = fmaf(x0, m4.z, acc[0][2]);
            acc[0][3] = fmaf(x0, m4.w, acc[0][3]);
            acc[1][0] = fmaf(x1, m4.x, acc[1][0]);
            acc[1][1] = fmaf(x1, m4.y, acc[1][1]);
            acc[1][2] = fmaf(x1, m4.z, acc[1][2]);
            acc[1][3] = fmaf(x1, m4.w, acc[1][3]);
            acc[2][0] = fmaf(x2, m4.x, acc[2][0]);
            acc[2][1] = fmaf(x2, m4.y, acc[2][1]);
            acc[2][2] = fmaf(x2, m4.z, acc[2][2]);
            acc[2][3] = fmaf(x2, m4.w, acc[2][3]);
            acc[3][0] = fmaf(x3, m4.x, acc[3][0]);
            acc[3][1] = fmaf(x3, m4.y, acc[3][1]);
            acc[3][2] = fmaf(x3, m4.z, acc[3][2]);
            acc[3][3] = fmaf(x3, m4.w, acc[3][3]);
        }
        __syncthreads();
    }

    // write transposed: u[(b*768 + d)*1024 + t], t contiguous per thread (float4)
#pragma unroll
    for (int j = 0; j < 4; ++j) {
        float4 v = make_float4(acc[0][j], acc[1][j], acc[2][j], acc[3][j]);
        *(float4*)&g_u[(size_t)(b * DD + d0 + tx * 4 + j) * TT + t0 + ty * 4] = v;
    }
}

// ---------------------------------------------------------------------------
// Kernel 3: per-channel diagonal LDS scan + direct taps.
// One warp per channel; 4 states per lane (s = lane + 32q).
// OUTPUT: float32, but rounded through bf16 to match the reference's
// astype(bfloat16) (harness compares in f32).
// ---------------------------------------------------------------------------
__global__ __launch_bounds__(128) void lds_kernel(float* __restrict__ out)
{
    const int w    = threadIdx.x >> 5;
    const int lane = threadIdx.x & 31;
    const int ch   = blockIdx.x * 4 + w;
    const int b = ch / DD;
    const int d = ch - b * DD;

    const float* uc = g_u + (size_t)ch * TT;
    const float a0 = g_A[lane],      a1 = g_A[lane + 32],
                a2 = g_A[lane + 64], a3 = g_A[lane + 96];
    const float* wd = g_wt + d * SS;
    const float w0 = wd[lane],      w1 = wd[lane + 32],
                w2 = wd[lane + 64], w3 = wd[lane + 96];
    const float* gd = g_gd + d * KX;
    const float gd0 = gd[0], gd1 = gd[1], gd2 = gd[2], gd3 = gd[3], gd4 = gd[4];

    float h0 = 0.f, h1 = 0.f, h2 = 0.f, h3 = 0.f;

    for (int r = 0; r < TT / 32; ++r) {
        const int base = r * 32;
        const float uv = uc[base + lane];
        float y = 0.f;
#pragma unroll
        for (int j = 0; j < 32; ++j) {
            float ut = __shfl_sync(0xffffffffu, uv, j);
            h0 = fmaf(a0, h0, ut);
            h1 = fmaf(a1, h1, ut);
            h2 = fmaf(a2, h2, ut);
            h3 = fmaf(a3, h3, ut);
            float p = fmaf(w0, h0, fmaf(w1, h1, fmaf(w2, h2, w3 * h3)));
            p += __shfl_xor_sync(0xffffffffu, p, 16);
            p += __shfl_xor_sync(0xffffffffu, p, 8);
            p += __shfl_xor_sync(0xffffffffu, p, 4);
            p += __shfl_xor_sync(0xffffffffu, p, 2);
            p += __shfl_xor_sync(0xffffffffu, p, 1);
            if (lane == j) y = p;
        }

        const int t = base + lane;
        y = fmaf(gd0, uv, y);
        if (t >= 1) y = fmaf(gd1, uc[t - 1], y);
        if (t >= 2) y = fmaf(gd2, uc[t - 2], y);
        if (t >= 3) y = fmaf(gd3, uc[t - 3], y);
        if (t >= 4) y = fmaf(gd4, uc[t - 4], y);

        // round through bf16 (reference casts to bfloat16), store as f32
        out[((size_t)b * TT + t) * DD + d] = __bfloat162float(__float2bfloat16(y));
    }
}

// ---------------------------------------------------------------------------
// Launch. Inputs resolved BY ELEMENT COUNT:
//   x=1572864  M_inputs=589824  M_filters=18432  C=6144  M_dir=240
//   A/Bm both 128 -> disambiguated at runtime by sign (A is uniform(0,1)).
// Output: float32 (b,T,d) row-major.
// ---------------------------------------------------------------------------
extern "C" void kernel_launch(void* const* d_in, const int* in_sizes, int n_in,
                              void* d_out, int out_size)
{
    const float* x = 0; const float* Mi = 0; const float* Mf = 0;
    const float* v128a = 0; const float* v128b = 0; const float* C = 0;
    const float* Mdir = 0;

    for (int i = 0; i < n_in; ++i) {
        int sz = in_sizes[i];
        const float* p = (const float*)d_in[i];
        if      (sz == BSZ * TT * DD)      x = p;
        else if (sz == DD * DD)            Mi = p;
        else if (sz == KK * DD)            Mf = p;
        else if (sz == 2 * KK * SS)        C = p;
        else if (sz == 2 * KK * KX)        Mdir = p;
        else if (sz == SS) { if (!v128a) v128a = p; else v128b = p; }
    }

    float* out = (float*)d_out;

    resolve_kernel<<<1, SS>>>(v128a, v128b);
    prep_kernel<<<DD, SS>>>(Mf, C, Mdir);
    gemm_kernel<<<dim3(DD / 64, TT / 64, BSZ), 256>>>(x, Mi);
    lds_kernel<<<NCH / 4, 128>>>(out);
}

// round 5
// speedup vs baseline: 1.4572x; 1.4572x over previous
#include <cuda_runtime.h>
#include <cuda_bf16.h>
#include <stdint.h>

// Problem constants
#define BSZ 2
#define TT  1024
#define DD  768
#define KK  24
#define SS  128
#define KX  5
#define NCH (BSZ*DD)   // 1536 channels

// Static device scratch
__device__ float g_u[NCH * TT];        // u[(b*768+d)*1024 + t]
__device__ float g_wt[DD * SS];        // folded readout weight w~[d][s]
__device__ float g_gd[DD * KX];        // folded direct taps gdir[d][j]
__device__ float g_A[SS];              // resolved decay A
__device__ float g_Bm[SS];             // resolved input map Bm

// packed f32x2 helpers (sm_100: fma.rn.f32x2 doubles fp32 FMA throughput)
#define FMA_F32X2(d, a, b, c) \
    asm("fma.rn.f32x2 %0, %1, %2, %3;" : "=l"(d) : "l"(a), "l"(b), "l"(c))
#define PACK_F32X2(out, lo, hi) \
    asm("mov.b64 %0, {%1, %2};" : "=l"(out) : "r"(lo), "r"(hi))

// ---------------------------------------------------------------------------
// Kernel 0: resolve A (uniform(0,1): all >= 0) vs Bm (has negatives).
// ---------------------------------------------------------------------------
__global__ void resolve_kernel(const float* __restrict__ p0,
                               const float* __restrict__ p1)
{
    __shared__ int neg0;
    if (threadIdx.x == 0) neg0 = 0;
    __syncthreads();
    if (p0[threadIdx.x] < 0.f) atomicAdd(&neg0, 1);
    __syncthreads();
    const float* Ap = (neg0 > 0) ? p1 : p0;
    const float* Bp = (neg0 > 0) ? p0 : p1;
    g_A[threadIdx.x]  = Ap[threadIdx.x];
    g_Bm[threadIdx.x] = Bp[threadIdx.x];
}

// ---------------------------------------------------------------------------
// Kernel 1: fold weights.
// ---------------------------------------------------------------------------
__global__ void prep_kernel(const float* __restrict__ Mf,    // (24,768)
                            const float* __restrict__ C,     // (48,128)
                            const float* __restrict__ Mdir)  // (48,5)
{
    int d = blockIdx.x;
    int s = threadIdx.x;
    float acc = 0.f;
#pragma unroll
    for (int k = 0; k < KK; ++k) {
        float mf = Mf[k * DD + d];
        acc += mf * (C[k * SS + s] + C[(KK + k) * SS + s]);
    }
    g_wt[d * SS + s] = acc * g_Bm[s];
    if (s < KX) {
        float a = 0.f;
#pragma unroll
        for (int k = 0; k < KK; ++k) {
            float mf = Mf[k * DD + d];
            a += mf * (Mdir[k * KX + s] + Mdir[(KK + k) * KX + s]);
        }
        g_gd[d * KX + s] = a;
    }
}

// ---------------------------------------------------------------------------
// Kernel 2: u[(b,d),t] = sum_c x[b,t,c] * M[c,d]  via packed FFMA2.
// 64(t) x 64(d) tile, BK=32, 128 threads.
// Micro-tile per thread: 8 t (as 4 f32x2 pairs) x 4 d.
// X tile stored transposed [c][t] (stride 66, even -> 8B-aligned b64 loads).
// ---------------------------------------------------------------------------
__global__ __launch_bounds__(128) void gemm_kernel(const float* __restrict__ x,  // (2,1024,768)
                                                   const float* __restrict__ M)  // (768,768)
{
    __shared__ float Xs[32][66];   // [c][t], even stride for b64 loads
    __shared__ float Ms[32][64];   // [c][d]

    const int b  = blockIdx.z;
    const int t0 = blockIdx.y * 64;
    const int d0 = blockIdx.x * 64;
    const int tid = threadIdx.x;
    const int tx = tid & 15;       // d group: 4 d's
    const int ty = tid >> 4;       // t group: 8 t's (4 pairs)

    unsigned long long acc[4][4];  // [t-pair][d], each = (y_t, y_{t+1})
#pragma unroll
    for (int i = 0; i < 4; ++i)
#pragma unroll
        for (int j = 0; j < 4; ++j) acc[i][j] = 0ull;

    const float* xb = x + ((size_t)b * TT + t0) * DD;

    for (int c0 = 0; c0 < DD; c0 += 32) {
        // X: 64 t-rows x 32 c; coalesced read, transposed write
#pragma unroll
        for (int i = 0; i < 16; ++i) {
            int idx = tid + i * 128;
            int c = idx & 31, tt = idx >> 5;
            Xs[c][tt] = xb[(size_t)tt * DD + c0 + c];
        }
        // M: 32 c-rows x 64 d; coalesced read & write
#pragma unroll
        for (int i = 0; i < 16; ++i) {
            int idx = tid + i * 128;
            int d = idx & 63, c = idx >> 6;
            Ms[c][d] = M[(size_t)(c0 + c) * DD + d0 + d];
        }
        __syncthreads();

#pragma unroll 8
        for (int kk = 0; kk < 32; ++kk) {
            // 4 x-pairs: (x_t, x_{t+1}) directly from smem (aligned b64)
            unsigned long long xp[4];
#pragma unroll
            for (int p = 0; p < 4; ++p)
                xp[p] = *(const unsigned long long*)&Xs[kk][ty * 8 + 2 * p];
            // 4 m scalars, duplicated into pairs
            float4 m4 = *(const float4*)&Ms[kk][tx * 4];
            unsigned long long mp[4];
            PACK_F32X2(mp[0], __float_as_uint(m4.x), __float_as_uint(m4.x));
            PACK_F32X2(mp[1], __float_as_uint(m4.y), __float_as_uint(m4.y));
            PACK_F32X2(mp[2], __float_as_uint(m4.z), __float_as_uint(m4.z));
            PACK_F32X2(mp[3], __float_as_uint(m4.w), __float_as_uint(m4.w));
#pragma unroll
            for (int p = 0; p < 4; ++p)
#pragma unroll
                for (int j = 0; j < 4; ++j)
                    FMA_F32X2(acc[p][j], xp[p], mp[j], acc[p][j]);
        }
        __syncthreads();
    }

    // store: u[(b*768 + d)*1024 + t]; t-pairs contiguous -> 8B stores
#pragma unroll
    for (int j = 0; j < 4; ++j) {
        int d = d0 + tx * 4 + j;
        float* ud = &g_u[((size_t)b * DD + d) * TT + t0 + ty * 8];
#pragma unroll
        for (int p = 0; p < 4; ++p)
            *(unsigned long long*)&ud[2 * p] = acc[p][j];
    }
}

// ---------------------------------------------------------------------------
// Kernel 3: per-channel diagonal LDS scan + direct taps.
// One warp per channel; 4 states per lane (s = lane + 32q).
// Per 32-step round: shuffle-broadcast u, update h, write partial dot to
// padded smem; then column-reduce (lane j owns t=base+j) with 4-way ILP.
// Output: f32 rounded through bf16.
// ---------------------------------------------------------------------------
__global__ __launch_bounds__(128) void lds_kernel(float* __restrict__ out)
{
    __shared__ float ps[4][32 * 33];
    const int w    = threadIdx.x >> 5;
    const int lane = threadIdx.x & 31;
    const int ch   = blockIdx.x * 4 + w;
    const int b = ch / DD;
    const int d = ch - b * DD;

    const float* uc = g_u + (size_t)ch * TT;
    const float a0 = g_A[lane],      a1 = g_A[lane + 32],
                a2 = g_A[lane + 64], a3 = g_A[lane + 96];
    const float* wd = g_wt + d * SS;
    const float w0 = wd[lane],      w1 = wd[lane + 32],
                w2 = wd[lane + 64], w3 = wd[lane + 96];
    const float* gd = g_gd + d * KX;
    const float gd0 = gd[0], gd1 = gd[1], gd2 = gd[2], gd3 = gd[3], gd4 = gd[4];

    float h0 = 0.f, h1 = 0.f, h2 = 0.f, h3 = 0.f;
    float* psw = ps[w];

    for (int r = 0; r < TT / 32; ++r) {
        const int base = r * 32;
        const float uv = uc[base + lane];
#pragma unroll
        for (int j = 0; j < 32; ++j) {
            float ut = __shfl_sync(0xffffffffu, uv, j);
            h0 = fmaf(a0, h0, ut);
            h1 = fmaf(a1, h1, ut);
            h2 = fmaf(a2, h2, ut);
            h3 = fmaf(a3, h3, ut);
            psw[lane * 33 + j] = fmaf(w0, h0, fmaf(w1, h1, fmaf(w2, h2, w3 * h3)));
        }
        __syncwarp();
        // column reduce with 4 independent accumulators (break the add chain)
        float y0 = 0.f, y1 = 0.f, y2 = 0.f, y3 = 0.f;
#pragma unroll
        for (int l = 0; l < 8; ++l) {
            y0 += psw[(l)      * 33 + lane];
            y1 += psw[(l + 8)  * 33 + lane];
            y2 += psw[(l + 16) * 33 + lane];
            y3 += psw[(l + 24) * 33 + lane];
        }
        float y = (y0 + y1) + (y2 + y3);

        const int t = base + lane;
        y = fmaf(gd0, uv, y);
        if (t >= 1) y = fmaf(gd1, uc[t - 1], y);
        if (t >= 2) y = fmaf(gd2, uc[t - 2], y);
        if (t >= 3) y = fmaf(gd3, uc[t - 3], y);
        if (t >= 4) y = fmaf(gd4, uc[t - 4], y);

        out[((size_t)b * TT + t) * DD + d] = __bfloat162float(__float2bfloat16(y));
        __syncwarp();
    }
}

// ---------------------------------------------------------------------------
// Launch. Inputs resolved BY ELEMENT COUNT; A/Bm disambiguated by sign.
// Output: float32 (b,T,d) row-major.
// ---------------------------------------------------------------------------
extern "C" void kernel_launch(void* const* d_in, const int* in_sizes, int n_in,
                              void* d_out, int out_size)
{
    const float* x = 0; const float* Mi = 0; const float* Mf = 0;
    const float* v128a = 0; const float* v128b = 0; const float* C = 0;
    const float* Mdir = 0;

    for (int i = 0; i < n_in; ++i) {
        int sz = in_sizes[i];
        const float* p = (const float*)d_in[i];
        if      (sz == BSZ * TT * DD)      x = p;
        else if (sz == DD * DD)            Mi = p;
        else if (sz == KK * DD)            Mf = p;
        else if (sz == 2 * KK * SS)        C = p;
        else if (sz == 2 * KK * KX)        Mdir = p;
        else if (sz == SS) { if (!v128a) v128a = p; else v128b = p; }
    }

    float* out = (float*)d_out;

    resolve_kernel<<<1, SS>>>(v128a, v128b);
    prep_kernel<<<DD, SS>>>(Mf, C, Mdir);
    gemm_kernel<<<dim3(DD / 64, TT / 64, BSZ), 128>>>(x, Mi);
    lds_kernel<<<NCH / 4, 128>>>(out);
}

// round 6
// speedup vs baseline: 1.5507x; 1.0641x over previous
#include <cuda_runtime.h>
#include <cuda_bf16.h>
#include <stdint.h>

// Problem constants
#define BSZ 2
#define TT  1024
#define DD  768
#define KK  24
#define SS  128
#define KX  5
#define NCH (BSZ*DD)   // 1536 channels
#define NC  8          // chunks per channel
#define CL  128        // chunk length (NC*CL == TT)

// Static device scratch
__device__ float g_u[NCH * TT];          // u[(b*768+d)*1024 + t]
__device__ float g_wt[DD * SS];          // folded readout weight w~[d][s]
__device__ float g_gd[DD * KX];          // folded direct taps gdir[d][j]
__device__ float g_A[SS];                // resolved decay A
__device__ float g_A128[SS];             // A^CL
__device__ float g_Bm[SS];               // resolved input map Bm
__device__ float g_hst[NCH * NC * SS];   // pass1: local end states -> pass1b: chunk start states

// ---------------------------------------------------------------------------
// Kernel 0: resolve A (uniform(0,1): all >= 0) vs Bm (has negatives),
// and precompute A^128 by squaring.
// ---------------------------------------------------------------------------
__global__ void resolve_kernel(const float* __restrict__ p0,
                               const float* __restrict__ p1)
{
    __shared__ int neg0;
    if (threadIdx.x == 0) neg0 = 0;
    __syncthreads();
    if (p0[threadIdx.x] < 0.f) atomicAdd(&neg0, 1);
    __syncthreads();
    const float* Ap = (neg0 > 0) ? p1 : p0;
    const float* Bp = (neg0 > 0) ? p0 : p1;
    float a = Ap[threadIdx.x];
    g_A[threadIdx.x]  = a;
    g_Bm[threadIdx.x] = Bp[threadIdx.x];
    float p = a;
#pragma unroll
    for (int i = 0; i < 7; ++i) p = p * p;   // a^128
    g_A128[threadIdx.x] = p;
}

// ---------------------------------------------------------------------------
// Kernel 1: fold weights.
//   wt[d][s] = Bm[s] * sum_k Mf[k][d] * (C[k][s] + C[K+k][s])
//   gd[d][j] = sum_k Mf[k][d] * (Mdir[k][j] + Mdir[K+k][j])
// ---------------------------------------------------------------------------
__global__ void prep_kernel(const float* __restrict__ Mf,    // (24,768)
                            const float* __restrict__ C,     // (48,128)
                            const float* __restrict__ Mdir)  // (48,5)
{
    int d = blockIdx.x;
    int s = threadIdx.x;
    float acc = 0.f;
#pragma unroll
    for (int k = 0; k < KK; ++k) {
        float mf = Mf[k * DD + d];
        acc += mf * (C[k * SS + s] + C[(KK + k) * SS + s]);
    }
    g_wt[d * SS + s] = acc * g_Bm[s];
    if (s < KX) {
        float a = 0.f;
#pragma unroll
        for (int k = 0; k < KK; ++k) {
            float mf = Mf[k * DD + d];
            a += mf * (Mdir[k * KX + s] + Mdir[(KK + k) * KX + s]);
        }
        g_gd[d * KX + s] = a;
    }
}

// ---------------------------------------------------------------------------
// Kernel 2: u[(b,d),t] = sum_c x[b,t,c] * M[c,d]   (transposed-output GEMM)
// 64(t) x 64(d) tile, BK=32, 256 threads, 4x4 microtile.  (R4-proven)
// ---------------------------------------------------------------------------
__global__ __launch_bounds__(256) void gemm_kernel(const float* __restrict__ x,  // (2,1024,768)
                                                   const float* __restrict__ M)  // (768,768)
{
    __shared__ float Xs[64][33];   // [t][c]  padded
    __shared__ float Ms[32][64];   // [c][d]

    int b  = blockIdx.z;
    int t0 = blockIdx.y * 64;
    int d0 = blockIdx.x * 64;
    int tid = threadIdx.x;
    int tx = tid & 15;           // d group (4 d each)
    int ty = tid >> 4;           // t group (4 t each)

    int lc = tid & 31;
    int lt = tid >> 5;
    int ldm = tid & 63;
    int lcm = tid >> 6;

    float acc[4][4] = {};

    const float* xb = x + (size_t)(b * TT + t0) * DD;

    for (int c0 = 0; c0 < DD; c0 += 32) {
#pragma unroll
        for (int i = 0; i < 8; ++i)
            Xs[lt * 8 + i][lc] = xb[(size_t)(lt * 8 + i) * DD + c0 + lc];
#pragma unroll
        for (int i = 0; i < 8; ++i)
            Ms[lcm * 8 + i][ldm] = M[(size_t)(c0 + lcm * 8 + i) * DD + d0 + ldm];
        __syncthreads();

#pragma unroll
        for (int kk = 0; kk < 32; ++kk) {
            float4 m4 = *(const float4*)&Ms[kk][tx * 4];
            float x0 = Xs[ty * 4 + 0][kk];
            float x1 = Xs[ty * 4 + 1][kk];
            float x2 = Xs[ty * 4 + 2][kk];
            float x3 = Xs[ty * 4 + 3][kk];
            acc[0][0] = fmaf(x0, m4.x, acc[0][0]);
            acc[0][1] = fmaf(x0, m4.y, acc[0][1]);
            acc[0][2] = fmaf(x0, m4.z, acc[0][2]);
            acc[0][3] = fmaf(x0, m4.w, acc[0][3]);
            acc[1][0] = fmaf(x1, m4.x, acc[1][0]);
            acc[1][1] = fmaf(x1, m4.y, acc[1][1]);
            acc[1][2] = fmaf(x1, m4.z, acc[1][2]);
            acc[1][3] = fmaf(x1, m4.w, acc[1][3]);
            acc[2][0] = fmaf(x2, m4.x, acc[2][0]);
            acc[2][1] = fmaf(x2, m4.y, acc[2][1]);
            acc[2][2] = fmaf(x2, m4.z, acc[2][2]);
            acc[2][3] = fmaf(x2, m4.w, acc[2][3]);
            acc[3][0] = fmaf(x3, m4.x, acc[3][0]);
            acc[3][1] = fmaf(x3, m4.y, acc[3][1]);
            acc[3][2] = fmaf(x3, m4.z, acc[3][2]);
            acc[3][3] = fmaf(x3, m4.w, acc[3][3]);
        }
        __syncthreads();
    }

#pragma unroll
    for (int j = 0; j < 4; ++j) {
        float4 v = make_float4(acc[0][j], acc[1][j], acc[2][j], acc[3][j]);
        *(float4*)&g_u[(size_t)(b * DD + d0 + tx * 4 + j) * TT + t0 + ty * 4] = v;
    }
}

// ---------------------------------------------------------------------------
// Kernel 3a (pass 1): local chunk end-states.
// Warp per (channel, chunk): run h = A*h + u for CL steps from h=0.
// Store end state to g_hst[(ch*NC + c)*SS + s].
// ---------------------------------------------------------------------------
__global__ __launch_bounds__(128) void state_kernel()
{
    const int w    = threadIdx.x >> 5;
    const int lane = threadIdx.x & 31;
    const int gw   = blockIdx.x * 4 + w;      // 0 .. NCH*NC-1
    const int ch   = gw >> 3;                 // NC == 8
    const int c    = gw & 7;

    const float* uc = g_u + (size_t)ch * TT + c * CL;
    const float a0 = g_A[lane],      a1 = g_A[lane + 32],
                a2 = g_A[lane + 64], a3 = g_A[lane + 96];

    float h0 = 0.f, h1 = 0.f, h2 = 0.f, h3 = 0.f;
#pragma unroll
    for (int r = 0; r < CL / 32; ++r) {
        const float uv = uc[r * 32 + lane];
#pragma unroll
        for (int j = 0; j < 32; ++j) {
            float ut = __shfl_sync(0xffffffffu, uv, j);
            h0 = fmaf(a0, h0, ut);
            h1 = fmaf(a1, h1, ut);
            h2 = fmaf(a2, h2, ut);
            h3 = fmaf(a3, h3, ut);
        }
    }
    float* hs = g_hst + (size_t)gw * SS;
    hs[lane]      = h0;
    hs[lane + 32] = h1;
    hs[lane + 64] = h2;
    hs[lane + 96] = h3;
}

// ---------------------------------------------------------------------------
// Kernel 3b (pass 1b): serial prefix-combine over chunks per channel.
// In-place: slot c becomes the START state H(c) for chunk c.
//   H(0)=0;  H(c+1) = A^CL * H(c) + h_loc(c)
// Warp per channel; 4 states per lane.
// ---------------------------------------------------------------------------
__global__ __launch_bounds__(128) void combine_kernel()
{
    const int w    = threadIdx.x >> 5;
    const int lane = threadIdx.x & 31;
    const int ch   = blockIdx.x * 4 + w;

    const float p0 = g_A128[lane],      p1 = g_A128[lane + 32],
                p2 = g_A128[lane + 64], p3 = g_A128[lane + 96];

    float H0 = 0.f, H1 = 0.f, H2 = 0.f, H3 = 0.f;
#pragma unroll
    for (int c = 0; c < NC; ++c) {
        float* hs = g_hst + ((size_t)ch * NC + c) * SS;
        float t0 = hs[lane], t1 = hs[lane + 32], t2 = hs[lane + 64], t3 = hs[lane + 96];
        hs[lane]      = H0;
        hs[lane + 32] = H1;
        hs[lane + 64] = H2;
        hs[lane + 96] = H3;
        H0 = fmaf(p0, H0, t0);
        H1 = fmaf(p1, H1, t1);
        H2 = fmaf(p2, H2, t2);
        H3 = fmaf(p3, H3, t3);
    }
}

// ---------------------------------------------------------------------------
// Kernel 3c (pass 2): scan with readout per chunk.
// Warp per (channel, chunk), init h = H(c), CL steps with dot via padded-smem
// transpose reduce, direct taps, bf16-rounded f32 output.
// ---------------------------------------------------------------------------
__global__ __launch_bounds__(128) void lds_kernel(float* __restrict__ out)
{
    __shared__ float ps[4][32 * 33];
    const int w    = threadIdx.x >> 5;
    const int lane = threadIdx.x & 31;
    const int gw   = blockIdx.x * 4 + w;
    const int ch   = gw >> 3;
    const int c    = gw & 7;
    const int b = ch / DD;
    const int d = ch - b * DD;

    const float* uch = g_u + (size_t)ch * TT;     // channel base (for taps)
    const float* uc  = uch + c * CL;
    const float a0 = g_A[lane],      a1 = g_A[lane + 32],
                a2 = g_A[lane + 64], a3 = g_A[lane + 96];
    const float* wd = g_wt + d * SS;
    const float w0 = wd[lane],      w1 = wd[lane + 32],
                w2 = wd[lane + 64], w3 = wd[lane + 96];
    const float* gd = g_gd + d * KX;
    const float gd0 = gd[0], gd1 = gd[1], gd2 = gd[2], gd3 = gd[3], gd4 = gd[4];

    const float* hs = g_hst + (size_t)gw * SS;
    float h0 = hs[lane], h1 = hs[lane + 32], h2 = hs[lane + 64], h3 = hs[lane + 96];

    float* psw = ps[w];

#pragma unroll
    for (int r = 0; r < CL / 32; ++r) {
        const int base = r * 32;
        const float uv = uc[base + lane];
#pragma unroll
        for (int j = 0; j < 32; ++j) {
            float ut = __shfl_sync(0xffffffffu, uv, j);
            h0 = fmaf(a0, h0, ut);
            h1 = fmaf(a1, h1, ut);
            h2 = fmaf(a2, h2, ut);
            h3 = fmaf(a3, h3, ut);
            psw[lane * 33 + j] = fmaf(w0, h0, fmaf(w1, h1, fmaf(w2, h2, w3 * h3)));
        }
        __syncwarp();
        float y0 = 0.f, y1 = 0.f, y2 = 0.f, y3 = 0.f;
#pragma unroll
        for (int l = 0; l < 8; ++l) {
            y0 += psw[(l)      * 33 + lane];
            y1 += psw[(l + 8)  * 33 + lane];
            y2 += psw[(l + 16) * 33 + lane];
            y3 += psw[(l + 24) * 33 + lane];
        }
        float y = (y0 + y1) + (y2 + y3);

        const int t = c * CL + base + lane;      // global time in channel
        y = fmaf(gd0, uv, y);
        if (t >= 1) y = fmaf(gd1, uch[t - 1], y);
        if (t >= 2) y = fmaf(gd2, uch[t - 2], y);
        if (t >= 3) y = fmaf(gd3, uch[t - 3], y);
        if (t >= 4) y = fmaf(gd4, uch[t - 4], y);

        out[((size_t)b * TT + t) * DD + d] = __bfloat162float(__float2bfloat16(y));
        __syncwarp();
    }
}

// ---------------------------------------------------------------------------
// Launch. Inputs resolved BY ELEMENT COUNT; A/Bm disambiguated by sign.
// Output: float32 (b,T,d) row-major.
// ---------------------------------------------------------------------------
extern "C" void kernel_launch(void* const* d_in, const int* in_sizes, int n_in,
                              void* d_out, int out_size)
{
    const float* x = 0; const float* Mi = 0; const float* Mf = 0;
    const float* v128a = 0; const float* v128b = 0; const float* C = 0;
    const float* Mdir = 0;

    for (int i = 0; i < n_in; ++i) {
        int sz = in_sizes[i];
        const float* p = (const float*)d_in[i];
        if      (sz == BSZ * TT * DD)      x = p;
        else if (sz == DD * DD)            Mi = p;
        else if (sz == KK * DD)            Mf = p;
        else if (sz == 2 * KK * SS)        C = p;
        else if (sz == 2 * KK * KX)        Mdir = p;
        else if (sz == SS) { if (!v128a) v128a = p; else v128b = p; }
    }

    float* out = (float*)d_out;

    resolve_kernel<<<1, SS>>>(v128a, v128b);
    prep_kernel<<<DD, SS>>>(Mf, C, Mdir);
    gemm_kernel<<<dim3(DD / 64, TT / 64, BSZ), 256>>>(x, Mi);
    state_kernel<<<NCH * NC / 4, 128>>>();
    combine_kernel<<<NCH / 4, 128>>>();
    lds_kernel<<<NCH * NC / 4, 128>>>(out);
}

// round 11
// speedup vs baseline: 1.8276x; 1.1786x over previous
#include <cuda_runtime.h>
#include <cuda_bf16.h>
#include <mma.h>
#include <stdint.h>

using namespace nvcuda;

// Problem constants
#define BSZ 2
#define TT  1024
#define DD  768
#define KK  24
#define SS  128
#define KX  5
#define NCH (BSZ*DD)   // 1536 channels
#define NC  8          // chunks per channel
#define CL  128        // chunk length (NC*CL == TT)
#define MM  (BSZ*TT)   // 2048 GEMM rows

// Static device scratch
__device__ float g_u[NCH * TT];          // u[(b*768+d)*1024 + t]
__device__ float g_wt[DD * SS];          // folded readout weight w~[d][s]
__device__ float g_gd[DD * KX];          // folded direct taps gdir[d][j]
__device__ float g_A[SS];                // resolved decay A
__device__ float g_A128[SS];             // A^CL
__device__ float g_Bm[SS];               // resolved input map Bm
__device__ float g_hst[NCH * NC * SS];   // chunk states
__device__ __nv_bfloat16 g_xh[MM * DD];  // x hi (bf16)
__device__ __nv_bfloat16 g_xl[MM * DD];  // x lo (bf16 residual)
__device__ __nv_bfloat16 g_mh[DD * DD];  // M hi
__device__ __nv_bfloat16 g_ml[DD * DD];  // M lo

// ---------------------------------------------------------------------------
// Kernel 0: resolve A (uniform(0,1): all >= 0) vs Bm (has negatives),
// and precompute A^128 by squaring.
// ---------------------------------------------------------------------------
__global__ void resolve_kernel(const float* __restrict__ p0,
                               const float* __restrict__ p1)
{
    __shared__ int neg0;
    if (threadIdx.x == 0) neg0 = 0;
    __syncthreads();
    if (p0[threadIdx.x] < 0.f) atomicAdd(&neg0, 1);
    __syncthreads();
    const float* Ap = (neg0 > 0) ? p1 : p0;
    const float* Bp = (neg0 > 0) ? p0 : p1;
    float a = Ap[threadIdx.x];
    g_A[threadIdx.x]  = a;
    g_Bm[threadIdx.x] = Bp[threadIdx.x];
    float p = a;
#pragma unroll
    for (int i = 0; i < 7; ++i) p = p * p;   // a^128
    g_A128[threadIdx.x] = p;
}

// ---------------------------------------------------------------------------
// Kernel 1: fold weights.
// ---------------------------------------------------------------------------
__global__ void prep_kernel(const float* __restrict__ Mf,    // (24,768)
                            const float* __restrict__ C,     // (48,128)
                            const float* __restrict__ Mdir)  // (48,5)
{
    int d = blockIdx.x;
    int s = threadIdx.x;
    float acc = 0.f;
#pragma unroll
    for (int k = 0; k < KK; ++k) {
        float mf = Mf[k * DD + d];
        acc += mf * (C[k * SS + s] + C[(KK + k) * SS + s]);
    }
    g_wt[d * SS + s] = acc * g_Bm[s];
    if (s < KX) {
        float a = 0.f;
#pragma unroll
        for (int k = 0; k < KK; ++k) {
            float mf = Mf[k * DD + d];
            a += mf * (Mdir[k * KX + s] + Mdir[(KK + k) * KX + s]);
        }
        g_gd[d * KX + s] = a;
    }
}

// ---------------------------------------------------------------------------
// Kernel 1b: split x and M into bf16 hi + bf16 residual.
// ---------------------------------------------------------------------------
__global__ void convert_kernel(const float* __restrict__ x,
                               const float* __restrict__ M)
{
    int i = blockIdx.x * 256 + threadIdx.x;
    if (i < MM * DD) {
        float v = x[i];
        __nv_bfloat16 h = __float2bfloat16(v);
        g_xh[i] = h;
        g_xl[i] = __float2bfloat16(v - __bfloat162float(h));
    }
    if (i < DD * DD) {
        float v = M[i];
        __nv_bfloat16 h = __float2bfloat16(v);
        g_mh[i] = h;
        g_ml[i] = __float2bfloat16(v - __bfloat162float(h));
    }
}

// ---------------------------------------------------------------------------
// Kernel 2: tensor-core GEMM via WMMA (no inline asm).
// u[(b,d),t] = sum_c x[m,c]*M[c,d], m = b*1024 + t.
// CTA tile 128m x 128n, BK=32, 8 warps (4m x 2n), warp tile 32x64.
// Split precision: acc = xh*mh + xh*ml + xl*mh, f32 accumulate.
// store_matrix_sync(mem_col_major, ldm=TT) writes directly transposed to g_u.
// ---------------------------------------------------------------------------
#define ASTR 48     // A smem row stride (bf16 units); 96B = multiple of 16B
#define BSTR 136    // B smem row stride; 272B = multiple of 16B

__global__ __launch_bounds__(256) void gemm_kernel()
{
    __shared__ __align__(32) __nv_bfloat16 Ah[128 * ASTR];
    __shared__ __align__(32) __nv_bfloat16 Al[128 * ASTR];
    __shared__ __align__(32) __nv_bfloat16 Bh[32 * BSTR];
    __shared__ __align__(32) __nv_bfloat16 Bl[32 * BSTR];

    const int tid = threadIdx.x;
    const int wid = tid >> 5;
    const int wm  = wid & 3;          // warp m position (4)
    const int wn  = wid >> 2;         // warp n position (2)

    const int m0 = blockIdx.y * 128;  // global row (b*1024 + t)
    const int d0 = blockIdx.x * 128;

    wmma::fragment<wmma::accumulator, 16, 16, 16, float> fc[2][4];
#pragma unroll
    for (int i = 0; i < 2; ++i)
#pragma unroll
        for (int j = 0; j < 4; ++j)
            wmma::fill_fragment(fc[i][j], 0.f);

    for (int c0 = 0; c0 < DD; c0 += 32) {
        // A tiles (xh, xl): 128 rows x 32 c, 16B chunks (512 chunks / 256 thr)
#pragma unroll
        for (int it = 0; it < 2; ++it) {
            int idx = tid + it * 256;
            int r = idx >> 2, q = idx & 3;
            *(uint4*)&Ah[r * ASTR + q * 8] =
                *(const uint4*)&g_xh[(size_t)(m0 + r) * DD + c0 + q * 8];
            *(uint4*)&Al[r * ASTR + q * 8] =
                *(const uint4*)&g_xl[(size_t)(m0 + r) * DD + c0 + q * 8];
        }
        // B tiles (mh, ml): 32 rows (c) x 128 d, 16B chunks
#pragma unroll
        for (int it = 0; it < 2; ++it) {
            int idx = tid + it * 256;
            int r = idx >> 4, q = idx & 15;
            *(uint4*)&Bh[r * BSTR + q * 8] =
                *(const uint4*)&g_mh[(size_t)(c0 + r) * DD + d0 + q * 8];
            *(uint4*)&Bl[r * BSTR + q * 8] =
                *(const uint4*)&g_ml[(size_t)(c0 + r) * DD + d0 + q * 8];
        }
        __syncthreads();

#pragma unroll
        for (int kc = 0; kc < 2; ++kc) {
            wmma::fragment<wmma::matrix_a, 16, 16, 16, __nv_bfloat16, wmma::row_major> fah[2], fal[2];
            wmma::fragment<wmma::matrix_b, 16, 16, 16, __nv_bfloat16, wmma::row_major> fbh[4], fbl[4];
#pragma unroll
            for (int i = 0; i < 2; ++i) {
                const __nv_bfloat16* pa = &Ah[(wm * 32 + i * 16) * ASTR + kc * 16];
                const __nv_bfloat16* pl = &Al[(wm * 32 + i * 16) * ASTR + kc * 16];
                wmma::load_matrix_sync(fah[i], pa, ASTR);
                wmma::load_matrix_sync(fal[i], pl, ASTR);
            }
#pragma unroll
            for (int j = 0; j < 4; ++j) {
                const __nv_bfloat16* pb = &Bh[(kc * 16) * BSTR + wn * 64 + j * 16];
                const __nv_bfloat16* pl = &Bl[(kc * 16) * BSTR + wn * 64 + j * 16];
                wmma::load_matrix_sync(fbh[j], pb, BSTR);
                wmma::load_matrix_sync(fbl[j], pl, BSTR);
            }
#pragma unroll
            for (int i = 0; i < 2; ++i)
#pragma unroll
                for (int j = 0; j < 4; ++j) {
                    wmma::mma_sync(fc[i][j], fah[i], fbh[j], fc[i][j]);
                    wmma::mma_sync(fc[i][j], fah[i], fbl[j], fc[i][j]);
                    wmma::mma_sync(fc[i][j], fal[i], fbh[j], fc[i][j]);
                }
        }
        __syncthreads();
    }

    // store transposed directly: col-major with ldm=TT puts element (m,n) at
    // dst[n*TT + m]  ->  g_u[(b*DD + d)*TT + t]
    const int mb = m0 + wm * 32;
    const int b  = mb >> 10;
    const int tb = mb & 1023;
#pragma unroll
    for (int i = 0; i < 2; ++i)
#pragma unroll
        for (int j = 0; j < 4; ++j) {
            int d = d0 + wn * 64 + j * 16;
            float* dst = &g_u[((size_t)b * DD + d) * TT + tb + i * 16];
            wmma::store_matrix_sync(dst, fc[i][j], TT, wmma::mem_col_major);
        }
}

// ---------------------------------------------------------------------------
// Kernel 3a (pass 1): local chunk end-states.
// ---------------------------------------------------------------------------
__global__ __launch_bounds__(128) void state_kernel()
{
    const int w    = threadIdx.x >> 5;
    const int lane = threadIdx.x & 31;
    const int gw   = blockIdx.x * 4 + w;
    const int ch   = gw >> 3;
    const int c    = gw & 7;

    const float* uc = g_u + (size_t)ch * TT + c * CL;
    const float a0 = g_A[lane],      a1 = g_A[lane + 32],
                a2 = g_A[lane + 64], a3 = g_A[lane + 96];

    float h0 = 0.f, h1 = 0.f, h2 = 0.f, h3 = 0.f;
#pragma unroll
    for (int r = 0; r < CL / 32; ++r) {
        const float uv = uc[r * 32 + lane];
#pragma unroll
        for (int j = 0; j < 32; ++j) {
            float ut = __shfl_sync(0xffffffffu, uv, j);
            h0 = fmaf(a0, h0, ut);
            h1 = fmaf(a1, h1, ut);
            h2 = fmaf(a2, h2, ut);
            h3 = fmaf(a3, h3, ut);
        }
    }
    float* hs = g_hst + (size_t)gw * SS;
    hs[lane]      = h0;
    hs[lane + 32] = h1;
    hs[lane + 64] = h2;
    hs[lane + 96] = h3;
}

// ---------------------------------------------------------------------------
// Kernel 3b: serial prefix-combine over chunks per channel (in-place).
// ---------------------------------------------------------------------------
__global__ __launch_bounds__(128) void combine_kernel()
{
    const int w    = threadIdx.x >> 5;
    const int lane = threadIdx.x & 31;
    const int ch   = blockIdx.x * 4 + w;

    const float p0 = g_A128[lane],      p1 = g_A128[lane + 32],
                p2 = g_A128[lane + 64], p3 = g_A128[lane + 96];

    float H0 = 0.f, H1 = 0.f, H2 = 0.f, H3 = 0.f;
#pragma unroll
    for (int c = 0; c < NC; ++c) {
        float* hs = g_hst + ((size_t)ch * NC + c) * SS;
        float t0 = hs[lane], t1 = hs[lane + 32], t2 = hs[lane + 64], t3 = hs[lane + 96];
        hs[lane]      = H0;
        hs[lane + 32] = H1;
        hs[lane + 64] = H2;
        hs[lane + 96] = H3;
        H0 = fmaf(p0, H0, t0);
        H1 = fmaf(p1, H1, t1);
        H2 = fmaf(p2, H2, t2);
        H3 = fmaf(p3, H3, t3);
    }
}

// ---------------------------------------------------------------------------
// Kernel 3c (pass 2): scan with readout per chunk.
// ---------------------------------------------------------------------------
__global__ __launch_bounds__(128) void lds_kernel(float* __restrict__ out)
{
    __shared__ float ps[4][32 * 33];
    const int w    = threadIdx.x >> 5;
    const int lane = threadIdx.x & 31;
    const int gw   = blockIdx.x * 4 + w;
    const int ch   = gw >> 3;
    const int c    = gw & 7;
    const int b = ch / DD;
    const int d = ch - b * DD;

    const float* uch = g_u + (size_t)ch * TT;
    const float* uc  = uch + c * CL;
    const float a0 = g_A[lane],      a1 = g_A[lane + 32],
                a2 = g_A[lane + 64], a3 = g_A[lane + 96];
    const float* wd = g_wt + d * SS;
    const float w0 = wd[lane],      w1 = wd[lane + 32],
                w2 = wd[lane + 64], w3 = wd[lane + 96];
    const float* gd = g_gd + d * KX;
    const float gd0 = gd[0], gd1 = gd[1], gd2 = gd[2], gd3 = gd[3], gd4 = gd[4];

    const float* hs = g_hst + (size_t)gw * SS;
    float h0 = hs[lane], h1 = hs[lane + 32], h2 = hs[lane + 64], h3 = hs[lane + 96];

    float* psw = ps[w];

#pragma unroll
    for (int r = 0; r < CL / 32; ++r) {
        const int base = r * 32;
        const float uv = uc[base + lane];
#pragma unroll
        for (int j = 0; j < 32; ++j) {
            float ut = __shfl_sync(0xffffffffu, uv, j);
            h0 = fmaf(a0, h0, ut);
            h1 = fmaf(a1, h1, ut);
            h2 = fmaf(a2, h2, ut);
            h3 = fmaf(a3, h3, ut);
            psw[lane * 33 + j] = fmaf(w0, h0, fmaf(w1, h1, fmaf(w2, h2, w3 * h3)));
        }
        __syncwarp();
        float y0 = 0.f, y1 = 0.f, y2 = 0.f, y3 = 0.f;
#pragma unroll
        for (int l = 0; l < 8; ++l) {
            y0 += psw[(l)      * 33 + lane];
            y1 += psw[(l + 8)  * 33 + lane];
            y2 += psw[(l + 16) * 33 + lane];
            y3 += psw[(l + 24) * 33 + lane];
        }
        float y = (y0 + y1) + (y2 + y3);

        const int t = c * CL + base + lane;
        y = fmaf(gd0, uv, y);
        if (t >= 1) y = fmaf(gd1, uch[t - 1], y);
        if (t >= 2) y = fmaf(gd2, uch[t - 2], y);
        if (t >= 3) y = fmaf(gd3, uch[t - 3], y);
        if (t >= 4) y = fmaf(gd4, uch[t - 4], y);

        out[((size_t)b * TT + t) * DD + d] = __bfloat162float(__float2bfloat16(y));
        __syncwarp();
    }
}

// ---------------------------------------------------------------------------
// Launch. Inputs resolved BY ELEMENT COUNT; A/Bm disambiguated by sign.
// Output: float32 (b,T,d) row-major.
// ---------------------------------------------------------------------------
extern "C" void kernel_launch(void* const* d_in, const int* in_sizes, int n_in,
                              void* d_out, int out_size)
{
    const float* x = 0; const float* Mi = 0; const float* Mf = 0;
    const float* v128a = 0; const float* v128b = 0; const float* C = 0;
    const float* Mdir = 0;

    for (int i = 0; i < n_in; ++i) {
        int sz = in_sizes[i];
        const float* p = (const float*)d_in[i];
        if      (sz == BSZ * TT * DD)      x = p;
        else if (sz == DD * DD)            Mi = p;
        else if (sz == KK * DD)            Mf = p;
        else if (sz == 2 * KK * SS)        C = p;
        else if (sz == 2 * KK * KX)        Mdir = p;
        else if (sz == SS) { if (!v128a) v128a = p; else v128b = p; }
    }

    float* out = (float*)d_out;

    resolve_kernel<<<1, SS>>>(v128a, v128b);
    prep_kernel<<<DD, SS>>>(Mf, C, Mdir);
    convert_kernel<<<(MM * DD + 255) / 256, 256>>>(x, Mi);
    gemm_kernel<<<dim3(DD / 128, MM / 128), 256>>>();
    state_kernel<<<NCH * NC / 4, 128>>>();
    combine_kernel<<<NCH / 4, 128>>>();
    lds_kernel<<<NCH * NC / 4, 128>>>(out);
}